// round 16
// baseline (speedup 1.0000x reference)
#include <cuda_runtime.h>
#include <math.h>
#include <stdint.h>

#define NG 8
#define GS 16
#define BR 32
#define TT 512
#define NTH 512
typedef unsigned long long ull;

__device__ float g_A[NG][256*BR];
__device__ float g_HD[NG][256*BR];
__device__ float g_OBS[NG][64*BR];
__device__ float g_NH0[2][NG][128*BR];
__device__ float g_NH1[2][NG][128*BR];
__device__ unsigned g_ctr[NG];

#define OMUS  0L
#define OSTDS 8388608L
#define ORETS 16777216L
#define OFIN  58720256L

// smem float offsets
#define O_WT1 0
#define O_WMS 1184
#define O_WD 3232
#define O_WRZ0 10560
#define O_WIN0 17888
#define O_WHN0 20528
#define O_WRZ1 21552
#define O_WIN1 25648
#define O_WHN1 26672
#define O_B1 27696
#define O_BS3 27712
#define O_BS4 27744
#define O_BD 27776
#define O_BMS 27792
#define O_X1 27800
#define O_ACT 30168
#define O_X4 44824
#define O_PART 53016
#define O_SCR 55064
#define O_SEQ 56088
#define SMEM_BYTES (56120*4)

__device__ __forceinline__ ull pk(float w) {
    ull r; asm("mov.b64 %0,{%1,%1};" : "=l"(r) : "f"(w)); return r;
}
__device__ __forceinline__ void fma2(ull& d, ull a, ull b) {
    asm("fma.rn.f32x2 %0,%1,%2,%0;" : "+l"(d) : "l"(a), "l"(b));
}
__device__ __forceinline__ float4 upk(ull lo, ull hi) {
    float4 v; *(ull*)&v.x = lo; *(ull*)&v.z = hi; return v;
}

__device__ __forceinline__ void bar_arrive(int g) {
    __syncthreads();
    if (threadIdx.x == 0)
        asm volatile("red.release.gpu.global.add.u32 [%0], 1;"
                     :: "l"(&g_ctr[g]) : "memory");
}
__device__ __forceinline__ void bar_wait(int g, unsigned tgt) {
    if (threadIdx.x == 0) {
        unsigned v;
        do {
            asm volatile("ld.acquire.gpu.global.u32 %0, [%1];"
                         : "=r"(v) : "l"(&g_ctr[g]) : "memory");
        } while (v < tgt);
    }
    __syncthreads();
}

// broadcast matvec: weights [K][NQ*4]; lane=row, warp=(q,kpart). NQ*KP==16.
template<int NQ,int KP,int TH>
__device__ __forceinline__ void bmv(const float* __restrict__ w, int K,
    const float* __restrict__ act, const float* __restrict__ bias,
    float* part, float* dst) {
    const int tid = threadIdx.x, lane = tid & 31, wid = tid >> 5;
    const int q = wid % NQ, p = wid / NQ;
    const int k0 = p * K / KP, k1 = (p + 1) * K / KP;
    const float* wp = w + q * 4;
    ull a0 = 0ull, a1 = 0ull;
    __syncthreads();
    const float* ap = act + lane;
#pragma unroll 4
    for (int k = k0; k < k1; k++) {
        ull pa = pk(ap[k * 32]);
        ulonglong2 wv = *(const ulonglong2*)(wp + k * (NQ * 4));
        fma2(a0, wv.x, pa); fma2(a1, wv.y, pa);
    }
    float4 acc = upk(a0, a1);
    part[((q*4+0)*KP + p)*32 + lane] = acc.x;
    part[((q*4+1)*KP + p)*32 + lane] = acc.y;
    part[((q*4+2)*KP + p)*32 + lane] = acc.z;
    part[((q*4+3)*KP + p)*32 + lane] = acc.w;
    __syncthreads();
    for (int o = tid; o < NQ*4*32; o += NTH) {
        int c = o >> 5, r = o & 31;
        float v = bias[c];
#pragma unroll
        for (int p2 = 0; p2 < KP; p2++) v += part[(c*KP + p2)*32 + r];
        dst[o] = TH ? tanhf(v) : v;
    }
    __syncthreads();
}

// fused GRU dots -> scr cols: 0-15 rz (K=Kx+128), 16-23 in (K=Kx), 24-31 hn (K=128)
__device__ __forceinline__ void grudot(const float* __restrict__ wrz,
    const float* __restrict__ win, const float* __restrict__ whn,
    int Kx, const float* __restrict__ act, const float* __restrict__ bias,
    float* part, float* scr) {
    const int tid = threadIdx.x, lane = tid & 31, wid = tid >> 5;
    const float* wp; int K, ao, ldw; float* pb; int q, p;
    if (wid < 8)       { q = wid & 3; p = wid >> 2; wp = wrz + q*4; ldw = 16;
                         K = Kx + 128; ao = 0; pb = part + (q*8 + p)*32; }
    else if (wid < 12) { int u = wid - 8; q = u & 1; p = u >> 1; wp = win + q*4;
                         ldw = 8; K = Kx; ao = 0; pb = part + 1024 + (q*8 + p)*32; }
    else               { int u = wid - 12; q = u & 1; p = u >> 1; wp = whn + q*4;
                         ldw = 8; K = 128; ao = Kx*32; pb = part + 1536 + (q*8 + p)*32; }
    const int k0 = p * K / 2, k1 = (p + 1) * K / 2;
    ull a0 = 0ull, a1 = 0ull;
    __syncthreads();
    const float* ap = act + ao + lane;
#pragma unroll 4
    for (int k = k0; k < k1; k++) {
        ull pa = pk(ap[k * 32]);
        ulonglong2 wv = *(const ulonglong2*)(wp + k * ldw);
        fma2(a0, wv.x, pa); fma2(a1, wv.y, pa);
    }
    float4 acc = upk(a0, a1);
    pb[0*64 + lane] = acc.x;
    pb[1*64 + lane] = acc.y;
    pb[2*64 + lane] = acc.z;
    pb[3*64 + lane] = acc.w;
    __syncthreads();
    for (int o = tid; o < 1024; o += NTH) {
        int c = o >> 5, r = o & 31;
        float v;
        if (c < 16)      v = bias[c] + part[(c*2)*32 + r]     + part[(c*2+1)*32 + r];
        else if (c < 24) { int ci = c-16;
                           v = bias[c] + part[1024 + ci*64 + r] + part[1024 + ci*64 + 32 + r]; }
        else             { int ci = c-24;
                           v = bias[c] + part[1536 + ci*64 + r] + part[1536 + ci*64 + 32 + r]; }
        scr[o] = v;
    }
    __syncthreads();
}

__device__ __forceinline__ void cpx(float* d, const float* s, int kc) {
    const float4* s4 = (const float4*)s; float4* d4 = (float4*)d;
#pragma unroll 4
    for (int i = threadIdx.x; i < kc*8; i += NTH) d4[i] = __ldcg(s4 + i);
}
__device__ __forceinline__ void cpx_mask(float* d, const float* s, int kc,
                                         const int* sq, int tp) {
    const float4* s4 = (const float4*)s; float4* d4 = (float4*)d;
#pragma unroll 4
    for (int i = threadIdx.x; i < kc*8; i += NTH) {
        float4 v = __ldcg(s4 + i); int r = (i & 7) * 4;
        if (tp >= sq[r+0]) v.x = 0.f; if (tp >= sq[r+1]) v.y = 0.f;
        if (tp >= sq[r+2]) v.z = 0.f; if (tp >= sq[r+3]) v.w = 0.f;
        d4[i] = v;
    }
}
__device__ __forceinline__ void cpt4(float* d, const float* s, int rs, int K) {
    int K4 = K >> 2;
#pragma unroll 2
    for (int i = threadIdx.x; i < K4*BR; i += NTH) {
        int kq = i % K4, r = i / K4;
        float4 v = *(const float4*)(s + (size_t)r*rs + kq*4);
        d[(kq*4+0)*32+r]=v.x; d[(kq*4+1)*32+r]=v.y;
        d[(kq*4+2)*32+r]=v.z; d[(kq*4+3)*32+r]=v.w;
    }
}
__device__ __forceinline__ void cpt2(float* d, const float* s, int rs, int K) {
    int K2 = K >> 1;
    for (int i = threadIdx.x; i < K2*BR; i += NTH) {
        int kq = i % K2, r = i / K2;
        float2 v = *(const float2*)(s + (size_t)r*rs + kq*2);
        d[(kq*2+0)*32+r]=v.x; d[(kq*2+1)*32+r]=v.y;
    }
}
__device__ __forceinline__ float sigf(float x){ return 1.f/(1.f+expf(-x)); }

__global__ void dynarnn_init() { if (threadIdx.x < NG) g_ctr[threadIdx.x] = 0u; }

__global__ void __launch_bounds__(NTH,1)
dynarnn_main(const float* __restrict__ obp, const float* __restrict__ acp,
             const float* __restrict__ noisep, const float* __restrict__ prevp,
             const int* __restrict__ seqp,
             const float* __restrict__ Wih0, const float* __restrict__ Whh0,
             const float* __restrict__ bih0, const float* __restrict__ bhh0,
             const float* __restrict__ Wih1, const float* __restrict__ Whh1,
             const float* __restrict__ bih1, const float* __restrict__ bhh1,
             const float* __restrict__ Wt1p, const float* __restrict__ bt1p,
             const float* __restrict__ Wt2p, const float* __restrict__ bt2p,
             const float* __restrict__ Wd1p, const float* __restrict__ bd1p,
             const float* __restrict__ Wmup, const float* __restrict__ bmup,
             const float* __restrict__ Wsdp, const float* __restrict__ bsdp,
             float* __restrict__ out)
{
    extern __shared__ float sm[];
    const int tid = threadIdx.x;
    const int g = blockIdx.x >> 4, ct = blockIdx.x & 15;
    float *wt1 = sm+O_WT1, *wms = sm+O_WMS, *wd = sm+O_WD;
    float *wrz0 = sm+O_WRZ0, *win0 = sm+O_WIN0, *whn0 = sm+O_WHN0;
    float *wrz1 = sm+O_WRZ1, *win1 = sm+O_WIN1, *whn1 = sm+O_WHN1;
    float *b1 = sm+O_B1, *bS3 = sm+O_BS3, *bS4 = sm+O_BS4;
    float *bd = sm+O_BD, *bms = sm+O_BMS;
    float *sX1 = sm+O_X1, *sAct = sm+O_ACT, *sX4 = sm+O_X4;
    float *part = sm+O_PART, *scr = sm+O_SCR;
    int *sseq = (int*)(sm+O_SEQ);

    // ---- weight loads ([K][C]) with nos-folding ----
    for (int i = tid; i < 74*16; i += NTH) {
        int k = i >> 4, c = i & 15;
        wt1[i] = Wt1p[k*256 + ct*16 + c];
    }
    for (int i = tid; i < 256*8; i += NTH) {
        int k = i >> 3, c = i & 7;
        wms[i] = (c < 4) ? Wmup[k*64 + ct*4 + c] : Wsdp[k*64 + ct*4 + (c-4)];
    }
    // wrz0: act layout [ob(64)|a(256)|ac(10)|h(128)], K=458
    for (int i = tid; i < 458*16; i += NTH) {
        int k = i >> 4, c = i & 15;
        int j = (c < 8) ? ct*8 + c : 128 + ct*8 + (c - 8);
        float v;
        if (k < 64) v = Wih0[j*138 + k];
        else if (k < 320) {
            int ka = k - 64; v = 0.f;
            const float* w2 = Wt2p + ka*64; const float* wi = Wih0 + j*138 + 64;
#pragma unroll 4
            for (int m = 0; m < 64; m++) v = fmaf(w2[m], wi[m], v);
        }
        else if (k < 330) v = Wih0[j*138 + 128 + (k - 320)];
        else v = Whh0[j*128 + (k - 330)];
        wrz0[i] = v;
    }
    for (int i = tid; i < 330*8; i += NTH) {
        int k = i >> 3, c = i & 7;
        int j = 256 + ct*8 + c;
        float v;
        if (k < 64) v = Wih0[j*138 + k];
        else if (k < 320) {
            int ka = k - 64; v = 0.f;
            const float* w2 = Wt2p + ka*64; const float* wi = Wih0 + j*138 + 64;
#pragma unroll 4
            for (int m = 0; m < 64; m++) v = fmaf(w2[m], wi[m], v);
        }
        else v = Wih0[j*138 + 128 + (k - 320)];
        win0[i] = v;
    }
    // wd: act layout [ob|a|ac|out], K=458 (Wd1 input order: out,nos,ob,ac)
    for (int i = tid; i < 458*16; i += NTH) {
        int k = i >> 4, c = i & 15, col = ct*16 + c;
        float v;
        if (k < 64) v = Wd1p[(192 + k)*256 + col];
        else if (k < 320) {
            int ka = k - 64; v = 0.f;
            const float* w2 = Wt2p + ka*64;
#pragma unroll 4
            for (int m = 0; m < 64; m++) v = fmaf(w2[m], Wd1p[(128+m)*256 + col], v);
        }
        else if (k < 330) v = Wd1p[(256 + (k - 320))*256 + col];
        else v = Wd1p[(k - 330)*256 + col];
        wd[i] = v;
    }
    for (int i = tid; i < 256*16; i += NTH) {
        int k = i >> 4, c = i & 15;
        int j = (c < 8) ? ct*8 + c : 128 + ct*8 + (c - 8);
        wrz1[i] = (k < 128) ? Wih1[j*128 + k] : Whh1[j*128 + (k - 128)];
    }
    for (int i = tid; i < 128*8; i += NTH) {
        int k = i >> 3, c = i & 7;
        whn0[i] = Whh0[(256 + ct*8 + c)*128 + k];
        win1[i] = Wih1[(256 + ct*8 + c)*128 + k];
        whn1[i] = Whh1[(256 + ct*8 + c)*128 + k];
    }
    if (tid < 16) {
        b1[tid] = bt1p[ct*16 + tid];
        float v = bd1p[ct*16 + tid];
        for (int m = 0; m < 64; m++) v = fmaf(bt2p[m], Wd1p[(128+m)*256 + ct*16 + tid], v);
        bd[tid] = v;
        int j = (tid < 8) ? ct*8 + tid : 128 + ct*8 + tid - 8;
        float f = 0.f;
        for (int m = 0; m < 64; m++) f = fmaf(bt2p[m], Wih0[j*138 + 64 + m], f);
        bS3[tid] = bih0[j] + bhh0[j] + f;
        bS4[tid] = bih1[j] + bhh1[j];
    } else if (tid < 32) {
        int q = tid - 16, j = 256 + ct*8 + (q & 7);
        if (q < 8) {
            float f = 0.f;
            for (int m = 0; m < 64; m++) f = fmaf(bt2p[m], Wih0[j*138 + 64 + m], f);
            bS3[tid] = bih0[j] + f;
            bS4[tid] = bih1[j];
        } else { bS3[tid] = bhh0[j]; bS4[tid] = bhh1[j]; }
    }
    if (tid < 8) bms[tid] = (tid < 4) ? bmup[ct*4 + tid] : bsdp[ct*4 + (tid-4)];
    if (tid < BR) sseq[tid] = seqp[g*BR + tid];
    for (int i = tid; i < 8*32; i += NTH) {
        int kk = i >> 5, r = i & 31, k = ct*8 + kk;
        const float* pv = prevp + (size_t)(g*BR + r) * 320;
        g_NH0[0][g][k*32 + r] = pv[k];
        g_NH1[0][g][k*32 + r] = pv[128 + k];
        if (kk < 4) { int k2 = ct*4 + kk; g_OBS[g][k2*32 + r] = pv[256 + k2]; }
    }
    unsigned nb = 1;
    bar_arrive(g); bar_wait(g, GS*nb); nb++;

    for (int t = 0; t < TT; t++) {
        float* nh0rd = g_NH0[t&1][g];       float* nh0wr = g_NH0[(t&1)^1][g];
        float* nh1rd = g_NH1[t&1][g];       float* nh1wr = g_NH1[(t&1)^1][g];
        const float* obT = obp + (size_t)g*BR*TT*64 + (size_t)t*64;
        const float* acT = acp + (size_t)g*BR*TT*10 + (size_t)t*10;
        float eps = 0.f;
        if (tid < 128) {
            size_t b = (size_t)(g*BR + (tid & 31));
            eps = __ldg(noisep + (b*TT + t)*64 + ct*4 + (tid >> 5));
        }
        // S1: a = tanh([obs, ac] @ Wt1 + bt1) -> g_A
        cpx(sX1, g_OBS[g], 64);
        cpt2(sX1 + 64*32, acT, TT*10, 10);
        bmv<4,4,1>(wt1, 74, sX1, b1, part, g_A[g] + ct*16*32);
        bar_arrive(g);
        // prefetch S3/S4 inputs inside barrier shadow
        cpt4(sAct, obT, TT*64, 64);
        cpt2(sAct + 320*32, acT, TT*10, 10);
        cpx_mask(sAct + 330*32, nh0rd, 128, sseq, t - 1);   // h0m
        cpx(sX4 + 128*32, nh1rd, 128);                      // h1m
        bar_wait(g, GS*nb); nb++;
        // S3: GRU0 on [ob|a|ac|h0m]
        cpx(sAct + 64*32, g_A[g], 256);
        grudot(wrz0, win0, whn0, 330, sAct, bS3, part, scr);
        float hm3 = 0.f; int cg3 = 0; size_t bb = 0;
        if (tid < 256) {
            int c = tid >> 5, r = tid & 31; cg3 = ct*8 + c;
            float rg = sigf(scr[c*32 + r]);
            float zg = sigf(scr[(8+c)*32 + r]);
            float ng = tanhf(scr[(16+c)*32 + r] + rg * scr[(24+c)*32 + r]);
            float hp = sAct[(330 + cg3)*32 + r];
            float nh = (1.f - zg)*ng + zg*hp;
            nh0wr[cg3*32 + r] = nh;
            hm3 = (t < sseq[r]) ? nh : 0.f;
            bb = (size_t)(g*BR + r);
        }
        bar_arrive(g);
        if (tid < 256) {
            out[ORETS + (bb*TT + t)*320 + cg3] = hm3;
            if (t == TT-1) out[OFIN + bb*320 + cg3] = hm3;
        }
        bar_wait(g, GS*nb); nb++;
        // S4: GRU1
        cpx(sX4, nh0wr, 128);
        grudot(wrz1, win1, whn1, 128, sX4, bS4, part, scr);
        float hm4 = 0.f;
        if (tid < 256) {
            int c = tid >> 5, r = tid & 31;
            float rg = sigf(scr[c*32 + r]);
            float zg = sigf(scr[(8+c)*32 + r]);
            float ng = tanhf(scr[(16+c)*32 + r] + rg * scr[(24+c)*32 + r]);
            float hp = sX4[(128 + cg3)*32 + r];
            float nh = (1.f - zg)*ng + zg*hp;
            hm4 = (t < sseq[r]) ? nh : 0.f;
            nh1wr[cg3*32 + r] = hm4;
        }
        bar_arrive(g);
        if (tid < 256) {
            out[ORETS + (bb*TT + t)*320 + 128 + cg3] = hm4;
            if (t == TT-1) out[OFIN + bb*320 + 128 + cg3] = hm4;
        }
        bar_wait(g, GS*nb); nb++;
        // S5: hdec = tanh([ob|a|ac|out] @ WdFold + bdFold) -> g_HD
        cpx(sAct + 330*32, nh1wr, 128);                     // out replaces h0m
        bmv<4,4,1>(wd, 458, sAct, bd, part, g_HD[g] + ct*16*32);
        bar_arrive(g); bar_wait(g, GS*nb); nb++;
        // S6: mu/std/ob_sim
        cpx(sX4, g_HD[g], 256);
        bmv<2,8,0>(wms, 256, sX4, bms, part, scr);
        float mu = 0.f, sd = 0.f, obs = 0.f; int cgl = 0;
        if (tid < 128) {
            int c = tid >> 5, r = tid & 31; cgl = ct*4 + c;
            mu = scr[c*32 + r];
            float sv = scr[(4+c)*32 + r];
            sd = fmaxf(sv, 0.f) + log1pf(expf(-fabsf(sv))) + 1e-4f;
            obs = fmaf(sd, eps, mu);
            g_OBS[g][cgl*32 + r] = obs;
        }
        bar_arrive(g);
        if (tid < 128) {
            size_t b = (size_t)(g*BR + (tid & 31));
            out[OMUS  + (b*TT + t)*64 + cgl] = mu;
            out[OSTDS + (b*TT + t)*64 + cgl] = sd;
            out[ORETS + (b*TT + t)*320 + 256 + cgl] = obs;
            if (t == TT-1) out[OFIN + b*320 + 256 + cgl] = obs;
        }
        bar_wait(g, GS*nb); nb++;
    }
}

extern "C" void kernel_launch(void* const* d_in, const int* in_sizes, int n_in,
                              void* d_out, int out_size) {
    cudaFuncSetAttribute(dynarnn_main, cudaFuncAttributeMaxDynamicSharedMemorySize, SMEM_BYTES);
    dynarnn_init<<<1, 32>>>();
    dynarnn_main<<<NG*GS, NTH, SMEM_BYTES>>>(
        (const float*)d_in[0], (const float*)d_in[1], (const float*)d_in[2],
        (const float*)d_in[3], (const int*)d_in[4],
        (const float*)d_in[5], (const float*)d_in[6], (const float*)d_in[7],
        (const float*)d_in[8], (const float*)d_in[9], (const float*)d_in[10],
        (const float*)d_in[11], (const float*)d_in[12],
        (const float*)d_in[13], (const float*)d_in[14], (const float*)d_in[15],
        (const float*)d_in[16], (const float*)d_in[17], (const float*)d_in[18],
        (const float*)d_in[19], (const float*)d_in[20], (const float*)d_in[21],
        (const float*)d_in[22], (float*)d_out);
}

// round 17
// speedup vs baseline: 1.0685x; 1.0685x over previous
#include <cuda_runtime.h>
#include <math.h>
#include <stdint.h>

#define NG 8
#define GS 16
#define BR 32
#define TT 512
#define NTH 512
typedef unsigned long long ull;

__device__ float g_A[NG][256*BR];
__device__ float g_NOS[NG][64*BR];
__device__ float g_HD[NG][256*BR];
__device__ float g_OBS[NG][64*BR];
__device__ float g_NH0[2][NG][128*BR];
__device__ float g_NH1[2][NG][128*BR];
__device__ unsigned g_ctr[NG];

#define OMUS  0L
#define OSTDS 8388608L
#define ORETS 16777216L
#define OFIN  58720256L

// smem float offsets (weights transposed: [K][C])
#define O_WT1 0
#define O_WT2 1184
#define O_WMS 2208
#define O_WD 4256
#define O_WRZ0 8512
#define O_WIN0 12768
#define O_WHN0 13872
#define O_WRZ1 14896
#define O_WIN1 18992
#define O_WHN1 20016
#define O_B1 21040
#define O_B2 21056
#define O_BS3 21064
#define O_BS4 21096
#define O_BD 21128
#define O_BMS 21144
#define O_X1 21152
#define O_ACT 31712
#define O_X4 40224
#define O_PART 48416
#define O_SCR 50464
#define O_SEQ 51488
#define SMEM_BYTES (51520*4)

__device__ __forceinline__ ull pk(float w) {
    ull r; asm("mov.b64 %0,{%1,%1};" : "=l"(r) : "f"(w)); return r;
}
__device__ __forceinline__ void fma2(ull& d, ull a, ull b) {
    asm("fma.rn.f32x2 %0,%1,%2,%0;" : "+l"(d) : "l"(a), "l"(b));
}
__device__ __forceinline__ float4 upk(ull lo, ull hi) {
    float4 v; *(ull*)&v.x = lo; *(ull*)&v.z = hi; return v;
}

__device__ __forceinline__ void bar_arrive(int g) {
    __syncthreads();
    if (threadIdx.x == 0)
        asm volatile("red.release.gpu.global.add.u32 [%0], 1;"
                     :: "l"(&g_ctr[g]) : "memory");
}
__device__ __forceinline__ void bar_wait(int g, unsigned tgt) {
    if (threadIdx.x == 0) {
        unsigned v;
        do {
            asm volatile("ld.acquire.gpu.global.u32 %0, [%1];"
                         : "=r"(v) : "l"(&g_ctr[g]) : "memory");
        } while (v < tgt);
    }
    __syncthreads();
}

// broadcast matvec, act in smem: weights [K][NQ*4]; lane=row, warp=(q,kpart).
template<int NQ,int KP,int TH>
__device__ __forceinline__ void bmv(const float* __restrict__ w, int K,
    const float* __restrict__ act, const float* __restrict__ bias,
    float* part, float* dst) {
    const int tid = threadIdx.x, lane = tid & 31, wid = tid >> 5;
    const int q = wid % NQ, p = wid / NQ;
    const int k0 = p * K / KP, k1 = (p + 1) * K / KP;
    const float* wp = w + q * 4;
    ull a0 = 0ull, a1 = 0ull;
    __syncthreads();
    const float* ap = act + lane;
#pragma unroll 4
    for (int k = k0; k < k1; k++) {
        ull pa = pk(ap[k * 32]);
        ulonglong2 wv = *(const ulonglong2*)(wp + k * (NQ * 4));
        fma2(a0, wv.x, pa); fma2(a1, wv.y, pa);
    }
    float4 acc = upk(a0, a1);
    part[((q*4+0)*KP + p)*32 + lane] = acc.x;
    part[((q*4+1)*KP + p)*32 + lane] = acc.y;
    part[((q*4+2)*KP + p)*32 + lane] = acc.z;
    part[((q*4+3)*KP + p)*32 + lane] = acc.w;
    __syncthreads();
    for (int o = tid; o < NQ*4*32; o += NTH) {
        int c = o >> 5, r = o & 31;
        float v = bias[c];
#pragma unroll
        for (int p2 = 0; p2 < KP; p2++) v += part[(c*KP + p2)*32 + r];
        dst[o] = TH ? tanhf(v) : v;
    }
    __syncthreads();
}

// broadcast matvec, act read DIRECTLY from global (coalesced __ldcg, no staging)
template<int NQ,int KP,int TH>
__device__ __forceinline__ void bmv_g(const float* __restrict__ w, int K,
    const float* __restrict__ gact, const float* __restrict__ bias,
    float* part, float* dst) {
    const int tid = threadIdx.x, lane = tid & 31, wid = tid >> 5;
    const int q = wid % NQ, p = wid / NQ;
    const int k0 = p * K / KP, k1 = (p + 1) * K / KP;
    const float* wp = w + q * 4;
    ull a0 = 0ull, a1 = 0ull;
    const float* ap = gact + lane;
#pragma unroll 8
    for (int k = k0; k < k1; k++) {
        ull pa = pk(__ldcg(ap + k * 32));
        ulonglong2 wv = *(const ulonglong2*)(wp + k * (NQ * 4));
        fma2(a0, wv.x, pa); fma2(a1, wv.y, pa);
    }
    float4 acc = upk(a0, a1);
    part[((q*4+0)*KP + p)*32 + lane] = acc.x;
    part[((q*4+1)*KP + p)*32 + lane] = acc.y;
    part[((q*4+2)*KP + p)*32 + lane] = acc.z;
    part[((q*4+3)*KP + p)*32 + lane] = acc.w;
    __syncthreads();
    for (int o = tid; o < NQ*4*32; o += NTH) {
        int c = o >> 5, r = o & 31;
        float v = bias[c];
#pragma unroll
        for (int p2 = 0; p2 < KP; p2++) v += part[(c*KP + p2)*32 + r];
        dst[o] = TH ? tanhf(v) : v;
    }
    __syncthreads();
}

// fused GRU dots -> scr cols: 0-15 rz (K=Kx+128), 16-23 in (K=Kx), 24-31 hn (K=128)
__device__ __forceinline__ void grudot(const float* __restrict__ wrz,
    const float* __restrict__ win, const float* __restrict__ whn,
    int Kx, const float* __restrict__ act, const float* __restrict__ bias,
    float* part, float* scr) {
    const int tid = threadIdx.x, lane = tid & 31, wid = tid >> 5;
    const float* wp; int K, ao, ldw; float* pb; int q, p;
    if (wid < 8)       { q = wid & 3; p = wid >> 2; wp = wrz + q*4; ldw = 16;
                         K = Kx + 128; ao = 0; pb = part + (q*8 + p)*32; }
    else if (wid < 12) { int u = wid - 8; q = u & 1; p = u >> 1; wp = win + q*4;
                         ldw = 8; K = Kx; ao = 0; pb = part + 1024 + (q*8 + p)*32; }
    else               { int u = wid - 12; q = u & 1; p = u >> 1; wp = whn + q*4;
                         ldw = 8; K = 128; ao = Kx*32; pb = part + 1536 + (q*8 + p)*32; }
    const int k0 = p * K / 2, k1 = (p + 1) * K / 2;
    ull a0 = 0ull, a1 = 0ull;
    __syncthreads();
    const float* ap = act + ao + lane;
#pragma unroll 4
    for (int k = k0; k < k1; k++) {
        ull pa = pk(ap[k * 32]);
        ulonglong2 wv = *(const ulonglong2*)(wp + k * ldw);
        fma2(a0, wv.x, pa); fma2(a1, wv.y, pa);
    }
    float4 acc = upk(a0, a1);
    pb[0*64 + lane] = acc.x;
    pb[1*64 + lane] = acc.y;
    pb[2*64 + lane] = acc.z;
    pb[3*64 + lane] = acc.w;
    __syncthreads();
    for (int o = tid; o < 1024; o += NTH) {
        int c = o >> 5, r = o & 31;
        float v;
        if (c < 16)      v = bias[c] + part[(c*2)*32 + r]     + part[(c*2+1)*32 + r];
        else if (c < 24) { int ci = c-16;
                           v = bias[c] + part[1024 + ci*64 + r] + part[1024 + ci*64 + 32 + r]; }
        else             { int ci = c-24;
                           v = bias[c] + part[1536 + ci*64 + r] + part[1536 + ci*64 + 32 + r]; }
        scr[o] = v;
    }
    __syncthreads();
}

__device__ __forceinline__ void cpx(float* d, const float* s, int kc) {
    const float4* s4 = (const float4*)s; float4* d4 = (float4*)d;
#pragma unroll 4
    for (int i = threadIdx.x; i < kc*8; i += NTH) d4[i] = __ldcg(s4 + i);
}
__device__ __forceinline__ void cpx_mask(float* d, const float* s, int kc,
                                         const int* sq, int tp) {
    const float4* s4 = (const float4*)s; float4* d4 = (float4*)d;
#pragma unroll 4
    for (int i = threadIdx.x; i < kc*8; i += NTH) {
        float4 v = __ldcg(s4 + i); int r = (i & 7) * 4;
        if (tp >= sq[r+0]) v.x = 0.f; if (tp >= sq[r+1]) v.y = 0.f;
        if (tp >= sq[r+2]) v.z = 0.f; if (tp >= sq[r+3]) v.w = 0.f;
        d4[i] = v;
    }
}
__device__ __forceinline__ void cpt4(float* d, const float* s, int rs, int K) {
    int K4 = K >> 2;
#pragma unroll 2
    for (int i = threadIdx.x; i < K4*BR; i += NTH) {
        int kq = i % K4, r = i / K4;
        float4 v = *(const float4*)(s + (size_t)r*rs + kq*4);
        d[(kq*4+0)*32+r]=v.x; d[(kq*4+1)*32+r]=v.y;
        d[(kq*4+2)*32+r]=v.z; d[(kq*4+3)*32+r]=v.w;
    }
}
__device__ __forceinline__ void cpt2(float* d, const float* s, int rs, int K) {
    int K2 = K >> 1;
    for (int i = threadIdx.x; i < K2*BR; i += NTH) {
        int kq = i % K2, r = i / K2;
        float2 v = *(const float2*)(s + (size_t)r*rs + kq*2);
        d[(kq*2+0)*32+r]=v.x; d[(kq*2+1)*32+r]=v.y;
    }
}
__device__ __forceinline__ float sigf(float x){ return 1.f/(1.f+expf(-x)); }

__global__ void dynarnn_init() { if (threadIdx.x < NG) g_ctr[threadIdx.x] = 0u; }

__global__ void __launch_bounds__(NTH,1)
dynarnn_main(const float* __restrict__ obp, const float* __restrict__ acp,
             const float* __restrict__ noisep, const float* __restrict__ prevp,
             const int* __restrict__ seqp,
             const float* __restrict__ Wih0, const float* __restrict__ Whh0,
             const float* __restrict__ bih0, const float* __restrict__ bhh0,
             const float* __restrict__ Wih1, const float* __restrict__ Whh1,
             const float* __restrict__ bih1, const float* __restrict__ bhh1,
             const float* __restrict__ Wt1p, const float* __restrict__ bt1p,
             const float* __restrict__ Wt2p, const float* __restrict__ bt2p,
             const float* __restrict__ Wd1p, const float* __restrict__ bd1p,
             const float* __restrict__ Wmup, const float* __restrict__ bmup,
             const float* __restrict__ Wsdp, const float* __restrict__ bsdp,
             float* __restrict__ out)
{
    extern __shared__ float sm[];
    const int tid = threadIdx.x;
    const int g = blockIdx.x >> 4, ct = blockIdx.x & 15;
    float *wt1 = sm+O_WT1, *wt2 = sm+O_WT2, *wms = sm+O_WMS, *wd = sm+O_WD;
    float *wrz0 = sm+O_WRZ0, *win0 = sm+O_WIN0, *whn0 = sm+O_WHN0;
    float *wrz1 = sm+O_WRZ1, *win1 = sm+O_WIN1, *whn1 = sm+O_WHN1;
    float *b1 = sm+O_B1, *b2 = sm+O_B2, *bS3 = sm+O_BS3, *bS4 = sm+O_BS4;
    float *bd = sm+O_BD, *bms = sm+O_BMS;
    float *sX1 = sm+O_X1, *sAct = sm+O_ACT, *sX4 = sm+O_X4;
    float *part = sm+O_PART, *scr = sm+O_SCR;
    int *sseq = (int*)(sm+O_SEQ);

    // ---- weight loads, transposed [K][C] ----
    for (int i = tid; i < 74*16; i += NTH) {
        int k = i >> 4, c = i & 15;
        wt1[i] = Wt1p[k*256 + ct*16 + c];
    }
    for (int i = tid; i < 256*4; i += NTH) {
        int k = i >> 2, c = i & 3;
        wt2[i] = Wt2p[k*64 + ct*4 + c];
    }
    for (int i = tid; i < 256*8; i += NTH) {
        int k = i >> 3, c = i & 7;
        wms[i] = (c < 4) ? Wmup[k*64 + ct*4 + c] : Wsdp[k*64 + ct*4 + (c-4)];
    }
    // Wd1 k-permuted so S5 act = [ob|nos|ac|out] reuses S3's buffer
    for (int i = tid; i < 266*16; i += NTH) {
        int k = i >> 4, c = i & 15;
        int ko = (k < 64) ? 192 + k : (k < 128) ? 64 + k :
                 (k < 138) ? 128 + k : k - 138;
        wd[i] = Wd1p[ko*256 + ct*16 + c];
    }
    for (int i = tid; i < 266*16; i += NTH) {
        int k = i >> 4, c = i & 15;
        int j = (c < 8) ? ct*8 + c : 128 + ct*8 + (c - 8);
        wrz0[i] = (k < 138) ? Wih0[j*138 + k] : Whh0[j*128 + (k - 138)];
    }
    for (int i = tid; i < 256*16; i += NTH) {
        int k = i >> 4, c = i & 15;
        int j = (c < 8) ? ct*8 + c : 128 + ct*8 + (c - 8);
        wrz1[i] = (k < 128) ? Wih1[j*128 + k] : Whh1[j*128 + (k - 128)];
    }
    for (int i = tid; i < 138*8; i += NTH) {
        int k = i >> 3, c = i & 7;
        win0[i] = Wih0[(256 + ct*8 + c)*138 + k];
    }
    for (int i = tid; i < 128*8; i += NTH) {
        int k = i >> 3, c = i & 7;
        whn0[i] = Whh0[(256 + ct*8 + c)*128 + k];
        win1[i] = Wih1[(256 + ct*8 + c)*128 + k];
        whn1[i] = Whh1[(256 + ct*8 + c)*128 + k];
    }
    if (tid < 16) {
        b1[tid] = bt1p[ct*16 + tid]; bd[tid] = bd1p[ct*16 + tid];
        int j = (tid < 8) ? ct*8 + tid : 128 + ct*8 + tid - 8;
        bS3[tid] = bih0[j] + bhh0[j]; bS4[tid] = bih1[j] + bhh1[j];
    } else if (tid < 32) {
        int q = tid - 16, j = 256 + ct*8 + (q & 7);
        if (q < 8) { bS3[tid] = bih0[j]; bS4[tid] = bih1[j]; }
        else       { bS3[tid] = bhh0[j]; bS4[tid] = bhh1[j]; }
    }
    if (tid < 4) { b2[tid] = bt2p[ct*4+tid]; bms[tid] = bmup[ct*4+tid]; bms[4+tid] = bsdp[ct*4+tid]; }
    if (tid < BR) sseq[tid] = seqp[g*BR + tid];
    for (int i = tid; i < 8*32; i += NTH) {
        int kk = i >> 5, r = i & 31, k = ct*8 + kk;
        const float* pv = prevp + (size_t)(g*BR + r) * 320;
        g_NH0[0][g][k*32 + r] = pv[k];
        g_NH1[0][g][k*32 + r] = pv[128 + k];
        if (kk < 4) { int k2 = ct*4 + kk; g_OBS[g][k2*32 + r] = pv[256 + k2]; }
    }
    unsigned nb = 1;
    bar_arrive(g); bar_wait(g, GS*nb); nb++;

    for (int t = 0; t < TT; t++) {
        float* nh0rd = g_NH0[t&1][g];       float* nh0wr = g_NH0[(t&1)^1][g];
        float* nh1rd = g_NH1[t&1][g];       float* nh1wr = g_NH1[(t&1)^1][g];
        const float* obT = obp + (size_t)g*BR*TT*64 + (size_t)t*64;
        const float* acT = acp + (size_t)g*BR*TT*10 + (size_t)t*10;
        float eps = 0.f;
        if (tid < 128) {
            size_t b = (size_t)(g*BR + (tid & 31));
            eps = __ldg(noisep + (b*TT + t)*64 + ct*4 + (tid >> 5));
        }
        // S1: a = tanh([obs, ac] @ Wt1 + bt1)
        cpx(sX1, g_OBS[g], 64);
        cpt2(sX1 + 64*32, acT, TT*10, 10);
        bmv<4,4,1>(wt1, 74, sX1, b1, part, g_A[g] + ct*16*32);
        bar_arrive(g);
        // prefetch S3/S4 inputs inside the barrier-wait shadow
        cpt4(sAct, obT, TT*64, 64);
        cpt2(sAct + 128*32, acT, TT*10, 10);
        cpx_mask(sAct + 138*32, nh0rd, 128, sseq, t - 1);   // h0m
        cpx(sX4 + 128*32, nh1rd, 128);                      // h1m
        bar_wait(g, GS*nb); nb++;
        // S2: nos = a @ Wt2 + bt2  (act direct from global g_A)
        bmv_g<1,16,0>(wt2, 256, g_A[g], b2, part, g_NOS[g] + ct*4*32);
        bar_arrive(g); bar_wait(g, GS*nb); nb++;
        // S3: GRU0
        cpx(sAct + 64*32, g_NOS[g], 64);
        grudot(wrz0, win0, whn0, 138, sAct, bS3, part, scr);
        float hm3 = 0.f; int cg3 = 0; size_t bb = 0;
        if (tid < 256) {
            int c = tid >> 5, r = tid & 31; cg3 = ct*8 + c;
            float rg = sigf(scr[c*32 + r]);
            float zg = sigf(scr[(8+c)*32 + r]);
            float ng = tanhf(scr[(16+c)*32 + r] + rg * scr[(24+c)*32 + r]);
            float hp = sAct[(138 + cg3)*32 + r];
            float nh = (1.f - zg)*ng + zg*hp;
            nh0wr[cg3*32 + r] = nh;
            hm3 = (t < sseq[r]) ? nh : 0.f;
            bb = (size_t)(g*BR + r);
        }
        bar_arrive(g);
        if (tid < 256) {
            out[ORETS + (bb*TT + t)*320 + cg3] = hm3;
            if (t == TT-1) out[OFIN + bb*320 + cg3] = hm3;
        }
        bar_wait(g, GS*nb); nb++;
        // S4: GRU1
        cpx(sX4, nh0wr, 128);
        grudot(wrz1, win1, whn1, 128, sX4, bS4, part, scr);
        float hm4 = 0.f;
        if (tid < 256) {
            int c = tid >> 5, r = tid & 31;
            float rg = sigf(scr[c*32 + r]);
            float zg = sigf(scr[(8+c)*32 + r]);
            float ng = tanhf(scr[(16+c)*32 + r] + rg * scr[(24+c)*32 + r]);
            float hp = sX4[(128 + cg3)*32 + r];
            float nh = (1.f - zg)*ng + zg*hp;
            hm4 = (t < sseq[r]) ? nh : 0.f;
            nh1wr[cg3*32 + r] = hm4;
        }
        bar_arrive(g);
        if (tid < 256) {
            out[ORETS + (bb*TT + t)*320 + 128 + cg3] = hm4;
            if (t == TT-1) out[OFIN + bb*320 + 128 + cg3] = hm4;
        }
        bar_wait(g, GS*nb); nb++;
        // S5: hdec = tanh([ob|nos|ac|out] @ Wd1perm + bd1)
        cpx(sAct + 138*32, nh1wr, 128);
        bmv<4,4,1>(wd, 266, sAct, bd, part, g_HD[g] + ct*16*32);
        bar_arrive(g); bar_wait(g, GS*nb); nb++;
        // S6: mu/std/ob_sim  (act direct from global g_HD)
        bmv_g<2,8,0>(wms, 256, g_HD[g], bms, part, scr);
        float mu = 0.f, sd = 0.f, obs = 0.f; int cgl = 0;
        if (tid < 128) {
            int c = tid >> 5, r = tid & 31; cgl = ct*4 + c;
            mu = scr[c*32 + r];
            float sv = scr[(4+c)*32 + r];
            sd = fmaxf(sv, 0.f) + log1pf(expf(-fabsf(sv))) + 1e-4f;
            obs = fmaf(sd, eps, mu);
            g_OBS[g][cgl*32 + r] = obs;
        }
        bar_arrive(g);
        if (tid < 128) {
            size_t b = (size_t)(g*BR + (tid & 31));
            out[OMUS  + (b*TT + t)*64 + cgl] = mu;
            out[OSTDS + (b*TT + t)*64 + cgl] = sd;
            out[ORETS + (b*TT + t)*320 + 256 + cgl] = obs;
            if (t == TT-1) out[OFIN + b*320 + 256 + cgl] = obs;
        }
        bar_wait(g, GS*nb); nb++;
    }
}

extern "C" void kernel_launch(void* const* d_in, const int* in_sizes, int n_in,
                              void* d_out, int out_size) {
    cudaFuncSetAttribute(dynarnn_main, cudaFuncAttributeMaxDynamicSharedMemorySize, SMEM_BYTES);
    dynarnn_init<<<1, 32>>>();
    dynarnn_main<<<NG*GS, NTH, SMEM_BYTES>>>(
        (const float*)d_in[0], (const float*)d_in[1], (const float*)d_in[2],
        (const float*)d_in[3], (const int*)d_in[4],
        (const float*)d_in[5], (const float*)d_in[6], (const float*)d_in[7],
        (const float*)d_in[8], (const float*)d_in[9], (const float*)d_in[10],
        (const float*)d_in[11], (const float*)d_in[12],
        (const float*)d_in[13], (const float*)d_in[14], (const float*)d_in[15],
        (const float*)d_in[16], (const float*)d_in[17], (const float*)d_in[18],
        (const float*)d_in[19], (const float*)d_in[20], (const float*)d_in[21],
        (const float*)d_in[22], (float*)d_out);
}